// round 1
// baseline (speedup 1.0000x reference)
#include <cuda_runtime.h>
#include <cstdint>

#define HH 2048
#define WW 2048
#define NPIX (HH*WW)

#define TH 64
#define TW 64
#define SH (TH+2)
#define SW (TW+2)

// Scratch (allocation-free rule: __device__ globals)
__device__ float g_bufA[NPIX];
__device__ float g_bufB[NPIX];
__device__ float g_good[NPIX];

// ---------------- Threefry-2x32 (exact JAX semantics) ----------------
__device__ __forceinline__ uint32_t rotl32(uint32_t x, int r) {
    return __funnelshift_l(x, x, r);
}

__device__ __forceinline__ void tf2x32(uint32_t k0, uint32_t k1,
                                       uint32_t x0, uint32_t x1,
                                       uint32_t& o0, uint32_t& o1) {
    uint32_t k2 = k0 ^ k1 ^ 0x1BD11BDAu;
    x0 += k0; x1 += k1;
#define TF_R4(a,b,c,d) \
    x0 += x1; x1 = rotl32(x1,a); x1 ^= x0; \
    x0 += x1; x1 = rotl32(x1,b); x1 ^= x0; \
    x0 += x1; x1 = rotl32(x1,c); x1 ^= x0; \
    x0 += x1; x1 = rotl32(x1,d); x1 ^= x0;
    TF_R4(13,15,26,6)   x0 += k1; x1 += k2 + 1u;
    TF_R4(17,29,16,24)  x0 += k2; x1 += k0 + 2u;
    TF_R4(13,15,26,6)   x0 += k0; x1 += k1 + 3u;
    TF_R4(17,29,16,24)  x0 += k1; x1 += k2 + 4u;
    TF_R4(13,15,26,6)   x0 += k2; x1 += k0 + 5u;
#undef TF_R4
    o0 = x0; o1 = x1;
}

// Host copy for key derivation (split of key(1) into 100 keys)
static inline uint32_t h_rotl32(uint32_t x, int r) { return (x << r) | (x >> (32 - r)); }
static void h_tf2x32(uint32_t k0, uint32_t k1, uint32_t x0, uint32_t x1,
                     uint32_t& o0, uint32_t& o1) {
    uint32_t k2 = k0 ^ k1 ^ 0x1BD11BDAu;
    x0 += k0; x1 += k1;
#define TF_R4(a,b,c,d) \
    x0 += x1; x1 = h_rotl32(x1,a); x1 ^= x0; \
    x0 += x1; x1 = h_rotl32(x1,b); x1 ^= x0; \
    x0 += x1; x1 = h_rotl32(x1,c); x1 ^= x0; \
    x0 += x1; x1 = h_rotl32(x1,d); x1 ^= x0;
    TF_R4(13,15,26,6)   x0 += k1; x1 += k2 + 1u;
    TF_R4(17,29,16,24)  x0 += k2; x1 += k0 + 2u;
    TF_R4(13,15,26,6)   x0 += k0; x1 += k1 + 3u;
    TF_R4(17,29,16,24)  x0 += k1; x1 += k2 + 4u;
    TF_R4(13,15,26,6)   x0 += k2; x1 += k0 + 5u;
#undef TF_R4
    o0 = x0; o1 = x1;
}

// ---------------- Kernels ----------------
__global__ __launch_bounds__(256) void init_kernel(
    const float* __restrict__ seed, const float* __restrict__ hab,
    const float* __restrict__ ter) {
    int i = blockIdx.x * 256 + threadIdx.x;
    g_bufA[i] = seed[i] * hab[i];
    g_good[i] = fmaxf(hab[i], ter[i]);
}

// One spread step: xs = src * (0.9 + 0.1*U(key, idx)); dst = max(maxpool3x3(xs)*good, src)
__global__ __launch_bounds__(256) void step_kernel(
    const float* __restrict__ src, float* __restrict__ dst,
    const float* __restrict__ good, uint32_t k0, uint32_t k1) {
    __shared__ float xs[SH][SW];

    const int r0 = blockIdx.y * TH;
    const int c0 = blockIdx.x * TW;
    const int tid = threadIdx.x;

    // Phase 1: fill randomized tile (with 1-px halo) into SMEM.
    // JAX partitionable threefry 32-bit bits: o0^o1 of cipher(key, (0, flat_idx)).
    #pragma unroll 1
    for (int idx = tid; idx < SH * SW; idx += 256) {
        int rr = idx / SW;
        int cc = idx - rr * SW;
        int row = r0 - 1 + rr;
        int col = c0 - 1 + cc;
        float v = 0.0f;  // SAME padding: all data >= 0, so 0 == -inf here
        if ((unsigned)row < HH && (unsigned)col < WW) {
            uint32_t j = (uint32_t)(row * WW + col);
            uint32_t o0, o1;
            tf2x32(k0, k1, 0u, j, o0, o1);
            uint32_t bits = o0 ^ o1;
            float u = __uint_as_float((bits >> 9) | 0x3f800000u) - 1.0f;
            float x = __ldg(&src[row * WW + col]);
            v = x * (0.9f + 0.1f * u);
        }
        xs[rr][cc] = v;
    }
    __syncthreads();

    // Phase 2: separable 3x3 max, rolling vertical window of row-maxes.
    // 256 threads = 64 cols x 4 row-strips of 16.
    const int c  = tid & 63;          // local col 0..63  -> smem col c..c+2
    const int rs = (tid >> 6) * 16;   // local row base   -> smem rows rs..rs+17
    const int col = c0 + c;

    float h0 = fmaxf(fmaxf(xs[rs    ][c], xs[rs    ][c+1]), xs[rs    ][c+2]);
    float h1 = fmaxf(fmaxf(xs[rs + 1][c], xs[rs + 1][c+1]), xs[rs + 1][c+2]);
    #pragma unroll
    for (int i = 0; i < 16; i++) {
        int sr = rs + i + 2;
        float h2 = fmaxf(fmaxf(xs[sr][c], xs[sr][c+1]), xs[sr][c+2]);
        float m = fmaxf(fmaxf(h0, h1), h2);
        int g = (r0 + rs + i) * WW + col;
        float xc = __ldg(&src[g]);
        dst[g] = fmaxf(m * __ldg(&good[g]), xc);
        h0 = h1; h1 = h2;
    }
}

__global__ __launch_bounds__(256) void final_kernel(
    const float* __restrict__ x, const float* __restrict__ hab,
    float* __restrict__ out) {
    int i = blockIdx.x * 256 + threadIdx.x;
    out[i] = x[i] * hab[i];
}

// ---------------- Launch ----------------
extern "C" void kernel_launch(void* const* d_in, const int* in_sizes, int n_in,
                              void* d_out, int out_size) {
    (void)in_sizes; (void)n_in; (void)out_size;
    const float* seedp = (const float*)d_in[0];
    const float* habp  = (const float*)d_in[1];
    const float* terp  = (const float*)d_in[2];
    float* outp = (float*)d_out;

    float *bufA = nullptr, *bufB = nullptr, *goodp = nullptr;
    cudaGetSymbolAddress((void**)&bufA, g_bufA);
    cudaGetSymbolAddress((void**)&bufB, g_bufB);
    cudaGetSymbolAddress((void**)&goodp, g_good);

    init_kernel<<<NPIX / 256, 256>>>(seedp, habp, terp);

    // keys = jax.random.split(jax.random.key(1), 100), partitionable:
    // key_t = threefry2x32((0,1), (0,t))
    uint32_t keys[100][2];
    for (uint32_t t = 0; t < 100; t++)
        h_tf2x32(0u, 1u, 0u, t, keys[t][0], keys[t][1]);

    dim3 grid(WW / TW, HH / TH);  // 32 x 32 blocks
    const float* s = bufA;
    float* d = bufB;
    for (int t = 0; t < 100; t++) {
        step_kernel<<<grid, 256>>>(s, d, goodp, keys[t][0], keys[t][1]);
        const float* tmp = d;
        d = (float*)s;
        s = tmp;
    }
    // 100 swaps -> result back in bufA; s points at it either way.
    final_kernel<<<NPIX / 256, 256>>>(s, habp, outp);
}

// round 3
// speedup vs baseline: 1.0585x; 1.0585x over previous
#include <cuda_runtime.h>
#include <cstdint>

#define HH 2048
#define WW 2048
#define NPIX (HH*WW)

#define TH 64
#define TW 64
#define SH (TH+2)
#define SW (TW+2)

// Scratch (allocation-free rule: __device__ globals)
__device__ float g_bufA[NPIX];
__device__ float g_bufB[NPIX];
__device__ float g_good[NPIX];

// ---------------- Threefry-2x32 (exact JAX semantics) ----------------
__device__ __forceinline__ uint32_t rotl32(uint32_t x, int r) {
    return __funnelshift_l(x, x, r);
}

// Add routed to the FMA pipe: mad.lo.u32 with an opaque multiplier (==1 at
// runtime, passed as kernel arg so ptxas cannot fold it to IADD3).
// Exact mod-2^32 => bit-identical to a plain add.
__device__ __forceinline__ uint32_t addf(uint32_t a, uint32_t b, uint32_t one) {
    uint32_t r;
    asm("mad.lo.u32 %0, %1, %2, %3;" : "=r"(r) : "r"(a), "r"(one), "r"(b));
    return r;
}

__device__ __forceinline__ void tf2x32(uint32_t k0, uint32_t k1,
                                       uint32_t x1in, uint32_t one,
                                       uint32_t& o0, uint32_t& o1) {
    // counter = (0, j): x0 starts as k0, x1 = j + k1
    uint32_t k2 = k0 ^ k1 ^ 0x1BD11BDAu;
    uint32_t x0 = k0;
    uint32_t x1 = addf(x1in, k1, one);
#define TF_R(rot) \
    x0 = addf(x0, x1, one); x1 = rotl32(x1, rot) ^ x0;
#define TF_R4(a,b,c,d) TF_R(a) TF_R(b) TF_R(c) TF_R(d)
    TF_R4(13,15,26,6)   x0 = addf(x0, k1, one); x1 = addf(x1, k2 + 1u, one);
    TF_R4(17,29,16,24)  x0 = addf(x0, k2, one); x1 = addf(x1, k0 + 2u, one);
    TF_R4(13,15,26,6)   x0 = addf(x0, k0, one); x1 = addf(x1, k1 + 3u, one);
    TF_R4(17,29,16,24)  x0 = addf(x0, k1, one); x1 = addf(x1, k2 + 4u, one);
    TF_R4(13,15,26,6)   x0 = addf(x0, k2, one); x1 = addf(x1, k0 + 5u, one);
#undef TF_R4
#undef TF_R
    o0 = x0; o1 = x1;
}

// Host copy for key derivation (split of key(1) into 100 keys)
static inline uint32_t h_rotl32(uint32_t x, int r) { return (x << r) | (x >> (32 - r)); }
static void h_tf2x32(uint32_t k0, uint32_t k1, uint32_t x0, uint32_t x1,
                     uint32_t& o0, uint32_t& o1) {
    uint32_t k2 = k0 ^ k1 ^ 0x1BD11BDAu;
    x0 += k0; x1 += k1;
#define TF_R4(a,b,c,d) \
    x0 += x1; x1 = h_rotl32(x1,a); x1 ^= x0; \
    x0 += x1; x1 = h_rotl32(x1,b); x1 ^= x0; \
    x0 += x1; x1 = h_rotl32(x1,c); x1 ^= x0; \
    x0 += x1; x1 = h_rotl32(x1,d); x1 ^= x0;
    TF_R4(13,15,26,6)   x0 += k1; x1 += k2 + 1u;
    TF_R4(17,29,16,24)  x0 += k2; x1 += k0 + 2u;
    TF_R4(13,15,26,6)   x0 += k0; x1 += k1 + 3u;
    TF_R4(17,29,16,24)  x0 += k1; x1 += k2 + 4u;
    TF_R4(13,15,26,6)   x0 += k2; x1 += k0 + 5u;
#undef TF_R4
    o0 = x0; o1 = x1;
}

// ---------------- Kernels ----------------
__global__ __launch_bounds__(256) void init_kernel(
    const float* __restrict__ seed, const float* __restrict__ hab,
    const float* __restrict__ ter) {
    int i = blockIdx.x * 256 + threadIdx.x;
    g_bufA[i] = seed[i] * hab[i];
    g_good[i] = fmaxf(hab[i], ter[i]);
}

// One spread step: xs = src * (0.9 + 0.1*U(key, idx)); dst = max(maxpool3x3(xs)*good, src)
// FINAL step additionally multiplies by habitat (fused epilogue).
template <bool FINAL>
__global__ __launch_bounds__(256) void step_kernel(
    const float* __restrict__ src, float* __restrict__ dst,
    const float* __restrict__ good, const float* __restrict__ hab,
    uint32_t k0, uint32_t k1, uint32_t one) {
    __shared__ float xs[SH][SW];

    const int r0 = blockIdx.y * TH;
    const int c0 = blockIdx.x * TW;
    const int tid = threadIdx.x;

    // Phase 1: fill randomized tile (with 1-px halo) into SMEM.
    // JAX partitionable threefry 32-bit bits: o0^o1 of cipher(key, (0, flat_idx)).
    for (int idx = tid; idx < SH * SW; idx += 256) {
        int rr = idx / SW;
        int cc = idx - rr * SW;
        int row = r0 - 1 + rr;
        int col = c0 - 1 + cc;
        float v = 0.0f;  // SAME padding: all data >= 0, so 0 == -inf here
        if ((unsigned)row < HH && (unsigned)col < WW) {
            uint32_t j = (uint32_t)(row * WW + col);
            uint32_t o0, o1;
            tf2x32(k0, k1, j, one, o0, o1);
            uint32_t bits = o0 ^ o1;
            float u = __uint_as_float((bits >> 9) | 0x3f800000u) - 1.0f;
            float x = __ldg(&src[row * WW + col]);
            v = x * (0.9f + 0.1f * u);
        }
        xs[rr][cc] = v;
    }
    __syncthreads();

    // Phase 2: separable 3x3 max, rolling vertical window of row-maxes.
    // 256 threads = 64 cols x 4 row-strips of 16.
    const int c  = tid & 63;          // local col 0..63  -> smem col c..c+2
    const int rs = (tid >> 6) * 16;   // local row base   -> smem rows rs..rs+17
    const int col = c0 + c;

    float h0 = fmaxf(fmaxf(xs[rs    ][c], xs[rs    ][c+1]), xs[rs    ][c+2]);
    float h1 = fmaxf(fmaxf(xs[rs + 1][c], xs[rs + 1][c+1]), xs[rs + 1][c+2]);
    #pragma unroll
    for (int i = 0; i < 16; i++) {
        int sr = rs + i + 2;
        float h2 = fmaxf(fmaxf(xs[sr][c], xs[sr][c+1]), xs[sr][c+2]);
        float m = fmaxf(fmaxf(h0, h1), h2);
        int g = (r0 + rs + i) * WW + col;
        float xc = __ldg(&src[g]);
        float res = fmaxf(m * __ldg(&good[g]), xc);
        if (FINAL) res *= __ldg(&hab[g]);
        dst[g] = res;
        h0 = h1; h1 = h2;
    }
}

// ---------------- Launch ----------------
extern "C" void kernel_launch(void* const* d_in, const int* in_sizes, int n_in,
                              void* d_out, int out_size) {
    (void)in_sizes; (void)n_in; (void)out_size;
    const float* seedp = (const float*)d_in[0];
    const float* habp  = (const float*)d_in[1];
    const float* terp  = (const float*)d_in[2];
    float* outp = (float*)d_out;

    float *bufA = nullptr, *bufB = nullptr, *goodp = nullptr;
    cudaGetSymbolAddress((void**)&bufA, g_bufA);
    cudaGetSymbolAddress((void**)&bufB, g_bufB);
    cudaGetSymbolAddress((void**)&goodp, g_good);

    init_kernel<<<NPIX / 256, 256>>>(seedp, habp, terp);

    // keys = jax.random.split(jax.random.key(1), 100), partitionable:
    // key_t = threefry2x32((0,1), (0,t))
    uint32_t keys[100][2];
    for (uint32_t t = 0; t < 100; t++)
        h_tf2x32(0u, 1u, 0u, t, keys[t][0], keys[t][1]);

    const uint32_t one = 1u;  // opaque to ptxas: keeps mad.lo as IMAD (fma pipe)

    dim3 grid(WW / TW, HH / TH);  // 32 x 32 blocks
    const float* s = bufA;
    float* d = bufB;
    for (int t = 0; t < 99; t++) {
        step_kernel<false><<<grid, 256>>>(s, d, goodp, habp,
                                          keys[t][0], keys[t][1], one);
        const float* tmp = d;
        d = (float*)s;
        s = tmp;
    }
    // Final step: fused * habitat epilogue, writes directly to d_out.
    step_kernel<true><<<grid, 256>>>(s, outp, goodp, habp,
                                     keys[99][0], keys[99][1], one);
}